// round 2
// baseline (speedup 1.0000x reference)
#include <cuda_runtime.h>

#define PH 7
#define PW 7
#define CC 128
#define HH 50
#define WW 50
#define SCALE 0.0625f

__global__ void roipool_kernel(const float* __restrict__ feat,
                               const float* __restrict__ rois,
                               float* __restrict__ out,
                               int total) {
    int idx = blockIdx.x * blockDim.x + threadIdx.x;
    if (idx >= total) return;

    int pw = idx % PW;
    int ph = (idx / PW) % PH;
    int c  = (idx / (PW * PH)) % CC;
    int k  =  idx / (PW * PH * CC);

    const float* r = rois + k * 5;
    int b  = (int)__ldg(r + 0);
    int x1 = (int)rintf(__ldg(r + 1) * SCALE);
    int y1 = (int)rintf(__ldg(r + 2) * SCALE);
    int x2 = (int)rintf(__ldg(r + 3) * SCALE);
    int y2 = (int)rintf(__ldg(r + 4) * SCALE);

    float roi_w = (float)max(x2 - x1 + 1, 1);
    float roi_h = (float)max(y2 - y1 + 1, 1);
    float bw = roi_w * (1.0f / PW);
    float bh = roi_h * (1.0f / PH);

    int hs = min(max((int)floorf((float)ph * bh) + y1, 0), HH);
    int he = min(max((int)ceilf((float)(ph + 1) * bh) + y1, 0), HH);
    int ws = min(max((int)floorf((float)pw * bw) + x1, 0), WW);
    int we = min(max((int)ceilf((float)(pw + 1) * bw) + x1, 0), WW);

    bool empty = (he <= hs) || (we <= ws);

    const float* f = feat + ((long)(b * CC + c)) * (HH * WW);
    float m = -3.402823466e+38f;
    for (int h = hs; h < he; h++) {
        const float* row = f + h * WW;
        for (int w = ws; w < we; w++) {
            m = fmaxf(m, __ldg(row + w));
        }
    }
    out[idx] = empty ? 0.0f : m;
}

extern "C" void kernel_launch(void* const* d_in, const int* in_sizes, int n_in,
                              void* d_out, int out_size) {
    const float* feat = (const float*)d_in[0];
    const float* rois = (const float*)d_in[1];
    float* out = (float*)d_out;
    int total = out_size;  // K*C*PH*PW = 256*128*7*7
    int threads = 256;
    int blocks = (total + threads - 1) / threads;
    roipool_kernel<<<blocks, threads>>>(feat, rois, out, total);
}